// round 16
// baseline (speedup 1.0000x reference)
#include <cuda_runtime.h>
#include <cuda_fp16.h>
#include <math.h>
#include <stdint.h>

#define B_   8
#define S_   56
#define C_   192
#define L_   3136
#define SO_  28
#define L2_  784
#define H_   3
#define D_   64

// ---------------- scratch (no allocs allowed) ----------------
__device__ __half g_hq[B_*L_*C_];
__device__ __half g_hk[B_*L2_*C_];
__device__ __half g_hv[B_*L2_*C_];
__device__ __half g_k [B_*L2_*C_];
__device__ __half g_v [B_*L2_*C_];
__device__ __half g_wq[C_*C_];   // pre-scaled by QSCALE
__device__ __half g_wk[C_*C_];
__device__ __half g_wv[C_*C_];

// ---------------- helpers ----------------
__device__ __forceinline__ void cp16(void* dst, const void* src) {
    uint32_t d = (uint32_t)__cvta_generic_to_shared(dst);
    asm volatile("cp.async.cg.shared.global [%0], [%1], 16;" :: "r"(d), "l"(src));
}
#define CP_COMMIT()   asm volatile("cp.async.commit_group;")
#define CP_WAIT0()    asm volatile("cp.async.wait_group 0;")

__device__ __forceinline__ uint32_t smem_u32(const void* p) {
    return (uint32_t)__cvta_generic_to_shared(p);
}
__device__ __forceinline__ float ex2(float x) {
    float r;
    asm("ex2.approx.f32 %0, %1;" : "=f"(r) : "f"(x));
    return r;
}
__device__ __forceinline__ uint32_t packh2(float a, float b) {
    __half2 h = __floats2half2_rn(a, b);
    return *(uint32_t*)&h;
}

// D += A(16x16) * B(16x8), fp16 inputs, fp32 accum
__device__ __forceinline__ void mma16(float* c,
                                      uint32_t a0, uint32_t a1, uint32_t a2, uint32_t a3,
                                      uint32_t b0, uint32_t b1) {
    asm volatile("mma.sync.aligned.m16n8k16.row.col.f32.f16.f16.f32 "
                 "{%0,%1,%2,%3}, {%4,%5,%6,%7}, {%8,%9}, {%0,%1,%2,%3};"
                 : "+f"(c[0]), "+f"(c[1]), "+f"(c[2]), "+f"(c[3])
                 : "r"(a0), "r"(a1), "r"(a2), "r"(a3), "r"(b0), "r"(b1));
}
#define LDM_X4(d0,d1,d2,d3,a) \
    asm volatile("ldmatrix.sync.aligned.m8n8.x4.shared.b16 {%0,%1,%2,%3}, [%4];" \
                 : "=r"(d0), "=r"(d1), "=r"(d2), "=r"(d3) : "r"(a))
#define LDM_X4T(d0,d1,d2,d3,a) \
    asm volatile("ldmatrix.sync.aligned.m8n8.x4.trans.shared.b16 {%0,%1,%2,%3}, [%4];" \
                 : "=r"(d0), "=r"(d1), "=r"(d2), "=r"(d3) : "r"(a))

// log2(e) folded into q projection weights (applied at conversion time).
#define QSCALE (0.125f * 1.44269504088896f)

// ---------------- depthwise 3x3 + BN: weights in SMEM (low reg peak) + W conversion ----------------
// grid (438, B): bx<196 = q strips, [196,294) = k/v strips (single pass),
// [294,438) (b==0 only) = W fp16 conversion.
__global__ void __launch_bounds__(192) dw_all(const float* __restrict__ x,
    const float* __restrict__ qdw, const float* __restrict__ qsc,
    const float* __restrict__ qbi, const float* __restrict__ qmu,
    const float* __restrict__ qva,
    const float* __restrict__ kdw, const float* __restrict__ ksc,
    const float* __restrict__ kbi, const float* __restrict__ kmu,
    const float* __restrict__ kva,
    const float* __restrict__ vdw, const float* __restrict__ vsc,
    const float* __restrict__ vbi, const float* __restrict__ vmu,
    const float* __restrict__ vva,
    const float* __restrict__ Wq, const float* __restrict__ Wk,
    const float* __restrict__ Wv)
{
    __shared__ float4 ws[2][9][48];    // per-block weight cache (block-uniform over ty)

    const int b = blockIdx.y;
    const int bxb = blockIdx.x;
    const int tx = threadIdx.x;
    const int tid = threadIdx.y * 48 + tx;

    if (bxb >= 294) {                      // ---- W fp32 -> fp16 conversion ----
        if (b != 0) return;
        int wb = bxb - 294;                // 0..143; 48 blocks per W
        const float* Wsrc = (wb < 48) ? Wq : (wb < 96) ? Wk : Wv;
        __half* Wd = (wb < 48) ? g_wq : (wb < 96) ? g_wk : g_wv;
        float s = (wb < 48) ? QSCALE : 1.0f;
        int local = (wb % 48) * 768 + tid * 4;
        float4 v = *(const float4*)&Wsrc[local];
        __half2* o = (__half2*)&Wd[local];
        o[0] = __floats2half2_rn(v.x * s, v.y * s);
        o[1] = __floats2half2_rn(v.z * s, v.w * s);
        return;
    }

    const int p = bxb * 4 + threadIdx.y;
    const int c = tx * 4;
    const float* xb = x + (size_t)b * L_ * C_ + c;

    if (bxb < 196) {
        // ---- q path (strips 0..783): weights to smem once per block ----
        #pragma unroll
        for (int i = 0; i < 3; i++) {
            int idx = tid + i * 192;
            if (idx < 432) {
                int t = idx / 48, qq = idx - t * 48;
                ws[0][t][qq] = *(const float4*)&qdw[t * C_ + qq * 4];
            }
        }
        __syncthreads();

        int y0 = (p / 56) * 4, xx = p % 56;
        float4 acc[4];
        #pragma unroll
        for (int i = 0; i < 4; i++) acc[i] = make_float4(0.f, 0.f, 0.f, 0.f);
        #pragma unroll
        for (int r = 0; r < 6; r++) {
            int iy = y0 - 1 + r;
            if ((unsigned)iy >= (unsigned)S_) continue;
            #pragma unroll
            for (int dx = 0; dx < 3; dx++) {
                int ix = xx + dx - 1;
                if ((unsigned)ix >= (unsigned)S_) continue;
                float4 xv = *(const float4*)&xb[(size_t)(iy * S_ + ix) * C_];
                #pragma unroll
                for (int i = 0; i < 4; i++) {
                    int dy = r - i;
                    if (dy < 0 || dy > 2) continue;
                    float4 wv = ws[0][dy * 3 + dx][tx];
                    acc[i].x += xv.x * wv.x; acc[i].y += xv.y * wv.y;
                    acc[i].z += xv.z * wv.z; acc[i].w += xv.w * wv.w;
                }
            }
        }
        float4 scv = *(const float4*)&qsc[c];
        float4 vav = *(const float4*)&qva[c];
        float4 muv = *(const float4*)&qmu[c];
        float4 biv = *(const float4*)&qbi[c];
        float a0 = scv.x * rsqrtf(vav.x + 1e-5f);
        float a1 = scv.y * rsqrtf(vav.y + 1e-5f);
        float a2 = scv.z * rsqrtf(vav.z + 1e-5f);
        float a3 = scv.w * rsqrtf(vav.w + 1e-5f);
        #pragma unroll
        for (int i = 0; i < 4; i++) {
            __half2* o = (__half2*)&g_hq[((size_t)b * L_ + (y0 + i) * S_ + xx) * C_ + c];
            o[0] = __floats2half2_rn((acc[i].x - muv.x) * a0 + biv.x,
                                     (acc[i].y - muv.y) * a1 + biv.y);
            o[1] = __floats2half2_rn((acc[i].z - muv.z) * a2 + biv.z,
                                     (acc[i].w - muv.w) * a3 + biv.w);
        }
    } else {
        // ---- k/v path: both weight sets to smem, SINGLE pass over x taps ----
        #pragma unroll
        for (int i = 0; i < 5; i++) {
            int idx = tid + i * 192;
            if (idx < 864) {
                int a = idx / 432;
                int r = idx - a * 432;
                int t = r / 48, qq = r - t * 48;
                const float* src = a ? vdw : kdw;
                ws[a][t][qq] = *(const float4*)&src[t * C_ + qq * 4];
            }
        }
        __syncthreads();

        int p2 = p - 784;
        int y0 = (p2 / SO_) * 2, xx = p2 % SO_;
        float4 ka[2], va[2];
        #pragma unroll
        for (int i = 0; i < 2; i++) {
            ka[i] = make_float4(0.f, 0.f, 0.f, 0.f);
            va[i] = make_float4(0.f, 0.f, 0.f, 0.f);
        }
        #pragma unroll
        for (int r = 0; r < 5; r++) {
            int iy = 2 * y0 + r;
            if (iy >= S_) continue;
            #pragma unroll
            for (int dx = 0; dx < 3; dx++) {
                int ix = 2 * xx + dx;
                if (ix >= S_) continue;
                float4 xv = *(const float4*)&xb[(size_t)(iy * S_ + ix) * C_];
                #pragma unroll
                for (int i = 0; i < 2; i++) {
                    int dy = r - 2 * i;
                    if (dy < 0 || dy > 2) continue;
                    float4 wk = ws[0][dy * 3 + dx][tx];
                    float4 wv = ws[1][dy * 3 + dx][tx];
                    ka[i].x += xv.x * wk.x; ka[i].y += xv.y * wk.y;
                    ka[i].z += xv.z * wk.z; ka[i].w += xv.w * wk.w;
                    va[i].x += xv.x * wv.x; va[i].y += xv.y * wv.y;
                    va[i].z += xv.z * wv.z; va[i].w += xv.w * wv.w;
                }
            }
        }
        {
            float4 scv = *(const float4*)&ksc[c];
            float4 vav = *(const float4*)&kva[c];
            float4 muv = *(const float4*)&kmu[c];
            float4 biv = *(const float4*)&kbi[c];
            float a0 = scv.x * rsqrtf(vav.x + 1e-5f);
            float a1 = scv.y * rsqrtf(vav.y + 1e-5f);
            float a2 = scv.z * rsqrtf(vav.z + 1e-5f);
            float a3 = scv.w * rsqrtf(vav.w + 1e-5f);
            #pragma unroll
            for (int i = 0; i < 2; i++) {
                __half2* o = (__half2*)&g_hk[((size_t)b * L2_ + (y0 + i) * SO_ + xx) * C_ + c];
                o[0] = __floats2half2_rn((ka[i].x - muv.x) * a0 + biv.x,
                                         (ka[i].y - muv.y) * a1 + biv.y);
                o[1] = __floats2half2_rn((ka[i].z - muv.z) * a2 + biv.z,
                                         (ka[i].w - muv.w) * a3 + biv.w);
            }
        }
        {
            float4 scv = *(const float4*)&vsc[c];
            float4 vav = *(const float4*)&vva[c];
            float4 muv = *(const float4*)&vmu[c];
            float4 biv = *(const float4*)&vbi[c];
            float a0 = scv.x * rsqrtf(vav.x + 1e-5f);
            float a1 = scv.y * rsqrtf(vav.y + 1e-5f);
            float a2 = scv.z * rsqrtf(vav.z + 1e-5f);
            float a3 = scv.w * rsqrtf(vav.w + 1e-5f);
            #pragma unroll
            for (int i = 0; i < 2; i++) {
                __half2* o = (__half2*)&g_hv[((size_t)b * L2_ + (y0 + i) * SO_ + xx) * C_ + c];
                o[0] = __floats2half2_rn((va[i].x - muv.x) * a0 + biv.x,
                                         (va[i].y - muv.y) * a1 + biv.y);
                o[1] = __floats2half2_rn((va[i].z - muv.z) * a2 + biv.z,
                                         (va[i].w - muv.w) * a3 + biv.w);
            }
        }
    }
}

// ---------------- pointwise 1x1 conv (k and v ONLY; q fused into attn) ----------------
#define PW_SMEM (128*200*2 + 192*72*2)
__global__ void __launch_bounds__(256) pw_all()
{
    const __half* A; const __half* Wh; __half* Cp; int m0;
    int bx = blockIdx.x;
    if (bx < 49) { A = g_hk; Cp = g_k; Wh = g_wk; m0 = bx * 128; }
    else         { A = g_hv; Cp = g_v; Wh = g_wv; m0 = (bx - 49) * 128; }
    const int n0 = blockIdx.y * 64;

    extern __shared__ char smc[];
    __half* As = (__half*)smc;
    __half* Bs = (__half*)(smc + 128 * 200 * 2);

    const int tid = threadIdx.x;
    const int w = tid >> 5, lane = tid & 31;
    const int g = lane >> 2, tg = lane & 3;
    const int lm = lane >> 3, lr = lane & 7;
    const uint32_t sAs = smem_u32(As), sBs = smem_u32(Bs);

    #pragma unroll
    for (int i = 0; i < 12; i++) {
        int idx = tid + i * 256;
        int r = idx / 24, ch = idx % 24;
        cp16(&As[r * 200 + ch * 8], A + (size_t)(m0 + r) * C_ + ch * 8);
    }
    #pragma unroll
    for (int i = 0; i < 6; i++) {
        int idx = tid + i * 256;
        int k = idx >> 3, nq = idx & 7;
        cp16(&Bs[k * 72 + nq * 8], Wh + (size_t)k * C_ + n0 + nq * 8);
    }
    CP_COMMIT();
    CP_WAIT0();
    __syncthreads();

    float Cv[8][4];
    #pragma unroll
    for (int i = 0; i < 8; i++)
        #pragma unroll
        for (int j = 0; j < 4; j++) Cv[i][j] = 0.f;

    const uint32_t aBase = sAs + (uint32_t)(((w * 16 + (lm & 1) * 8 + lr) * 200
                                             + (lm >> 1) * 8) * 2);
    const uint32_t bRow  = (uint32_t)(((lm & 1) * 8 + lr) * 72) * 2;
    #pragma unroll
    for (int ks = 0; ks < 12; ks++) {
        uint32_t a0, a1, a2, a3;
        LDM_X4(a0, a1, a2, a3, aBase + ks * 32);
        #pragma unroll
        for (int nfp = 0; nfp < 4; nfp++) {
            uint32_t b00, b01, b10, b11;
            uint32_t ba = sBs + (uint32_t)(ks * 16 * 72 * 2) + bRow
                        + (uint32_t)(((nfp * 2 + (lm >> 1)) * 8) * 2);
            LDM_X4T(b00, b01, b10, b11, ba);
            mma16(Cv[nfp * 2],     a0, a1, a2, a3, b00, b01);
            mma16(Cv[nfp * 2 + 1], a0, a1, a2, a3, b10, b11);
        }
    }

    const int r0 = 16 * w + g;
    __half* o0 = Cp + (size_t)(m0 + r0) * C_ + n0;
    __half* o1 = o0 + (size_t)8 * C_;
    #pragma unroll
    for (int nf = 0; nf < 8; nf++) {
        *(__half2*)&o0[nf * 8 + 2 * tg] = __floats2half2_rn(Cv[nf][0], Cv[nf][1]);
        *(__half2*)&o1[nf * 8 + 2 * tg] = __floats2half2_rn(Cv[nf][2], Cv[nf][3]);
    }
}

// ---------------- flash attention with fused q-projection ----------------
#define NKT 13
#define ATTN_SMEM ((128*72 + 4*64*72) * 2)
__global__ void __launch_bounds__(256, 2) attn_mma(float* __restrict__ out)
{
    extern __shared__ char smc[];
    __half* Qs = (__half*)smc;           // hq-chunk staging (128 x 72)
    __half* Ks = Qs + 128 * 72;          // double buffer; buf0 doubles as Wq staging
    __half* Vs = Ks + 2 * 64 * 72;

    const int tid = threadIdx.x;
    const int w = tid >> 5, lane = tid & 31;
    const int g = lane >> 2, tg = lane & 3;
    const int lm = lane >> 3, lr = lane & 7;
    const int q0 = blockIdx.x * 128;
    const int h = blockIdx.y, b = blockIdx.z;

    const __half* hqp = g_hq + (size_t)b * L_ * C_;
    const __half* kp = g_k + (size_t)b * L2_ * C_ + h * D_;
    const __half* vp = g_v + (size_t)b * L2_ * C_ + h * D_;

    const uint32_t aBaseQ = smem_u32(Qs) + (uint32_t)(((w * 16 + (lm & 1) * 8 + lr) * 72
                                                       + (lm >> 1) * 8) * 2);
    const uint32_t bRowW = (uint32_t)(((lm & 1) * 8 + lr) * 72) * 2;   // k-row (trans B)
    const uint32_t bRowK = (uint32_t)(((lm >> 1) * 8 + lr) * 72 * 2);  // QK: j rows
    const uint32_t bRowV = (uint32_t)(((lm & 1) * 8 + lr) * 72 * 2);   // PV: k rows, trans
    const uint32_t sK0 = smem_u32(Ks);

    // ---- q-projection: 3 chunks of K=64 ----
    float Qacc[8][4];
    #pragma unroll
    for (int i = 0; i < 8; i++)
        #pragma unroll
        for (int j = 0; j < 4; j++) Qacc[i][j] = 0.f;

    for (int cch = 0; cch < 3; cch++) {
        #pragma unroll
        for (int p = 0; p < 4; p++) {
            int id = tid + p * 256;
            int r = id >> 3, off = (id & 7) * 8;
            int rg = q0 + r; if (rg > L_ - 1) rg = L_ - 1;
            cp16(&Qs[r * 72 + off], hqp + (size_t)rg * C_ + cch * 64 + off);
        }
        #pragma unroll
        for (int p = 0; p < 2; p++) {
            int id = tid + p * 256;
            int kk = id >> 3, off = (id & 7) * 8;
            cp16(&Ks[kk * 72 + off], g_wq + (size_t)(cch * 64 + kk) * C_ + h * D_ + off);
        }
        CP_COMMIT();
        CP_WAIT0();
        __syncthreads();

        #pragma unroll
        for (int ks = 0; ks < 4; ks++) {
            uint32_t a0, a1, a2, a3;
            LDM_X4(a0, a1, a2, a3, aBaseQ + ks * 32);
            #pragma unroll
            for (int nfp = 0; nfp < 4; nfp++) {
                uint32_t b00, b01, b10, b11;
                uint32_t ba = sK0 + (uint32_t)(ks * 16 * 72 * 2) + bRowW
                            + (uint32_t)(((nfp * 2 + (lm >> 1)) * 8) * 2);
                LDM_X4T(b00, b01, b10, b11, ba);
                mma16(Qacc[nfp * 2],     a0, a1, a2, a3, b00, b01);
                mma16(Qacc[nfp * 2 + 1], a0, a1, a2, a3, b10, b11);
            }
        }
        __syncthreads();   // readers done before next chunk overwrites staging
    }

    // pack fp32 C-fragments -> fp16 A-fragments for QK^T (Wq pre-scaled by QSCALE)
    uint32_t Qa[4][4];
    #pragma unroll
    for (int ks = 0; ks < 4; ks++) {
        Qa[ks][0] = packh2(Qacc[2 * ks][0],     Qacc[2 * ks][1]);
        Qa[ks][1] = packh2(Qacc[2 * ks][2],     Qacc[2 * ks][3]);
        Qa[ks][2] = packh2(Qacc[2 * ks + 1][0], Qacc[2 * ks + 1][1]);
        Qa[ks][3] = packh2(Qacc[2 * ks + 1][2], Qacc[2 * ks + 1][3]);
    }

    // issue K+V tile 0 (buf 0 — safe after trailing syncthreads above)
    #pragma unroll
    for (int p = 0; p < 2; p++) {
        int id = tid + p * 256;
        int j = id >> 3, off = (id & 7) * 8;
        cp16(&Ks[j * 72 + off], kp + (size_t)j * C_ + off);
        cp16(&Vs[j * 72 + off], vp + (size_t)j * C_ + off);
    }
    CP_COMMIT();

    float Ov[8][4];
    #pragma unroll
    for (int i = 0; i < 8; i++)
        #pragma unroll
        for (int j = 0; j < 4; j++) Ov[i][j] = 0.f;
    float s0 = 0.f, s1 = 0.f;

    for (int kt = 0; kt < NKT; kt++) {
        CP_WAIT0();
        __syncthreads();

        if (kt + 1 < NKT) {
            int nb = (kt + 1) & 1;
            int j0n = (kt + 1) * 64;
            __half* Kb = Ks + nb * (64 * 72);
            __half* Vb = Vs + nb * (64 * 72);
            #pragma unroll
            for (int p = 0; p < 2; p++) {
                int id = tid + p * 256;
                int j = id >> 3, off = (id & 7) * 8;
                int jg = j0n + j; if (jg > L2_ - 1) jg = L2_ - 1;
                cp16(&Kb[j * 72 + off], kp + (size_t)jg * C_ + off);
                cp16(&Vb[j * 72 + off], vp + (size_t)jg * C_ + off);
            }
            CP_COMMIT();
        }

        const uint32_t sK = smem_u32(Ks + (kt & 1) * (64 * 72));
        const uint32_t sV = smem_u32(Vs + (kt & 1) * (64 * 72));

        // S = Q K^T : warp 16 x 64
        float Sc[8][4];
        #pragma unroll
        for (int i = 0; i < 8; i++)
            #pragma unroll
            for (int j = 0; j < 4; j++) Sc[i][j] = 0.f;
        #pragma unroll
        for (int ks = 0; ks < 4; ks++) {
            #pragma unroll
            for (int nfp = 0; nfp < 4; nfp++) {
                uint32_t b00, b01, b10, b11;
                uint32_t ba = sK + (uint32_t)(nfp * 16 * 72 * 2) + bRowK
                            + (uint32_t)((ks * 16 + (lm & 1) * 8) * 2);
                LDM_X4(b00, b01, b10, b11, ba);
                mma16(Sc[nfp * 2],     Qa[ks][0], Qa[ks][1], Qa[ks][2], Qa[ks][3], b00, b01);
                mma16(Sc[nfp * 2 + 1], Qa[ks][0], Qa[ks][1], Qa[ks][2], Qa[ks][3], b10, b11);
            }
        }

        int j0 = kt * 64;
        if (j0 + 64 > L2_) {             // mask invalid keys: exp2(-1e4) == 0
            #pragma unroll
            for (int nf = 0; nf < 8; nf++) {
                int c0 = j0 + nf * 8 + 2 * tg;
                if (c0 >= L2_)     { Sc[nf][0] = -1e4f; Sc[nf][2] = -1e4f; }
                if (c0 + 1 >= L2_) { Sc[nf][1] = -1e4f; Sc[nf][3] = -1e4f; }
            }
        }

        // P = exp2(S) directly (scores bounded); accumulate row sums in fp32
        uint32_t Pa[8][2];
        #pragma unroll
        for (int nf = 0; nf < 8; nf++) {
            float p00 = ex2(Sc[nf][0]);
            float p01 = ex2(Sc[nf][1]);
            float p10 = ex2(Sc[nf][2]);
            float p11 = ex2(Sc[nf][3]);
            s0 += p00 + p01; s1 += p10 + p11;
            Pa[nf][0] = packh2(p00, p01);
            Pa[nf][1] = packh2(p10, p11);
        }

        // O += P V   (A = P regs, B = V via ldmatrix.trans)
        #pragma unroll
        for (int ks = 0; ks < 4; ks++) {
            uint32_t a0 = Pa[2 * ks][0],     a1 = Pa[2 * ks][1];
            uint32_t a2 = Pa[2 * ks + 1][0], a3 = Pa[2 * ks + 1][1];
            #pragma unroll
            for (int dfp = 0; dfp < 4; dfp++) {
                uint32_t b00, b01, b10, b11;
                uint32_t ba = sV + (uint32_t)(ks * 16 * 72 * 2) + bRowV
                            + (uint32_t)(((dfp * 2 + (lm >> 1)) * 8) * 2);
                LDM_X4T(b00, b01, b10, b11, ba);
                mma16(Ov[dfp * 2],     a0, a1, a2, a3, b00, b01);
                mma16(Ov[dfp * 2 + 1], a0, a1, a2, a3, b10, b11);
            }
        }
    }

    // single final reduction of row sums over the quad
    s0 += __shfl_xor_sync(0xffffffffu, s0, 1);
    s0 += __shfl_xor_sync(0xffffffffu, s0, 2);
    s1 += __shfl_xor_sync(0xffffffffu, s1, 1);
    s1 += __shfl_xor_sync(0xffffffffu, s1, 2);

    // epilogue (fp32 output) — guard rows past L_ (last q-tile is ragged)
    float i0 = 1.f / s0, i1 = 1.f / s1;
    int rg0 = q0 + 16 * w + g;
    if (rg0 < L_) {
        float* o = out + ((size_t)b * L_ + rg0) * C_ + h * D_;
        #pragma unroll
        for (int df = 0; df < 8; df++)
            *(float2*)&o[df * 8 + 2 * tg] =
                make_float2(Ov[df][0] * i0, Ov[df][1] * i0);
    }
    int rg1 = rg0 + 8;
    if (rg1 < L_) {
        float* o = out + ((size_t)b * L_ + rg1) * C_ + h * D_;
        #pragma unroll
        for (int df = 0; df < 8; df++)
            *(float2*)&o[df * 8 + 2 * tg] =
                make_float2(Ov[df][2] * i1, Ov[df][3] * i1);
    }
}

// ---------------- launch ----------------
extern "C" void kernel_launch(void* const* d_in, const int* in_sizes, int n_in,
                              void* d_out, int out_size)
{
    const float* x       = (const float*)d_in[0];
    const float* q_dw    = (const float*)d_in[1];
    const float* q_scale = (const float*)d_in[2];
    const float* q_bias  = (const float*)d_in[3];
    const float* q_mean  = (const float*)d_in[4];
    const float* q_var   = (const float*)d_in[5];
    const float* q_pw    = (const float*)d_in[6];
    const float* k_dw    = (const float*)d_in[7];
    const float* k_scale = (const float*)d_in[8];
    const float* k_bias  = (const float*)d_in[9];
    const float* k_mean  = (const float*)d_in[10];
    const float* k_var   = (const float*)d_in[11];
    const float* k_pw    = (const float*)d_in[12];
    const float* v_dw    = (const float*)d_in[13];
    const float* v_scale = (const float*)d_in[14];
    const float* v_bias  = (const float*)d_in[15];
    const float* v_mean  = (const float*)d_in[16];
    const float* v_var   = (const float*)d_in[17];
    const float* v_pw    = (const float*)d_in[18];
    float* out = (float*)d_out;

    cudaFuncSetAttribute(pw_all,
                         cudaFuncAttributeMaxDynamicSharedMemorySize, PW_SMEM);
    cudaFuncSetAttribute(attn_mma,
                         cudaFuncAttributeMaxDynamicSharedMemorySize, ATTN_SMEM);

    dw_all<<<dim3(438, B_), dim3(48, 4)>>>(x,
        q_dw, q_scale, q_bias, q_mean, q_var,
        k_dw, k_scale, k_bias, k_mean, k_var,
        v_dw, v_scale, v_bias, v_mean, v_var,
        q_pw, k_pw, v_pw);

    pw_all<<<dim3(98, 3), 256, PW_SMEM>>>();

    attn_mma<<<dim3((L_ + 127) / 128, H_, B_), 256, ATTN_SMEM>>>(out);
}

// round 17
// speedup vs baseline: 1.0371x; 1.0371x over previous
#include <cuda_runtime.h>
#include <cuda_fp16.h>
#include <math.h>
#include <stdint.h>

#define B_   8
#define S_   56
#define C_   192
#define L_   3136
#define SO_  28
#define L2_  784
#define H_   3
#define D_   64

// ---------------- scratch (no allocs allowed) ----------------
__device__ __half g_hq[B_*L_*C_];
__device__ __half g_hk[B_*L2_*C_];
__device__ __half g_hv[B_*L2_*C_];
__device__ __half g_k [B_*L2_*C_];
__device__ __half g_v [B_*L2_*C_];
__device__ __half g_wq[C_*C_];   // pre-scaled by QSCALE
__device__ __half g_wk[C_*C_];
__device__ __half g_wv[C_*C_];

// ---------------- helpers ----------------
__device__ __forceinline__ void cp16(void* dst, const void* src) {
    uint32_t d = (uint32_t)__cvta_generic_to_shared(dst);
    asm volatile("cp.async.cg.shared.global [%0], [%1], 16;" :: "r"(d), "l"(src));
}
#define CP_COMMIT()   asm volatile("cp.async.commit_group;")
#define CP_WAIT0()    asm volatile("cp.async.wait_group 0;")
#define CP_WAIT1()    asm volatile("cp.async.wait_group 1;")

__device__ __forceinline__ uint32_t smem_u32(const void* p) {
    return (uint32_t)__cvta_generic_to_shared(p);
}
__device__ __forceinline__ float ex2(float x) {
    float r;
    asm("ex2.approx.f32 %0, %1;" : "=f"(r) : "f"(x));
    return r;
}
__device__ __forceinline__ uint32_t packh2(float a, float b) {
    __half2 h = __floats2half2_rn(a, b);
    return *(uint32_t*)&h;
}

// D += A(16x16) * B(16x8), fp16 inputs, fp32 accum
__device__ __forceinline__ void mma16(float* c,
                                      uint32_t a0, uint32_t a1, uint32_t a2, uint32_t a3,
                                      uint32_t b0, uint32_t b1) {
    asm volatile("mma.sync.aligned.m16n8k16.row.col.f32.f16.f16.f32 "
                 "{%0,%1,%2,%3}, {%4,%5,%6,%7}, {%8,%9}, {%0,%1,%2,%3};"
                 : "+f"(c[0]), "+f"(c[1]), "+f"(c[2]), "+f"(c[3])
                 : "r"(a0), "r"(a1), "r"(a2), "r"(a3), "r"(b0), "r"(b1));
}
#define LDM_X4(d0,d1,d2,d3,a) \
    asm volatile("ldmatrix.sync.aligned.m8n8.x4.shared.b16 {%0,%1,%2,%3}, [%4];" \
                 : "=r"(d0), "=r"(d1), "=r"(d2), "=r"(d3) : "r"(a))
#define LDM_X4T(d0,d1,d2,d3,a) \
    asm volatile("ldmatrix.sync.aligned.m8n8.x4.trans.shared.b16 {%0,%1,%2,%3}, [%4];" \
                 : "=r"(d0), "=r"(d1), "=r"(d2), "=r"(d3) : "r"(a))

// log2(e) folded into q projection weights (applied at conversion time).
#define QSCALE (0.125f * 1.44269504088896f)

// ---------------- depthwise 3x3 + BN (R15 form): hoisted weights, k/v two-pass ----------------
// grid (438, B): bx<294 = dw strips; bx in [294,438) (b==0 only) = W conversion.
__global__ void __launch_bounds__(192) dw_all(const float* __restrict__ x,
    const float* __restrict__ qdw, const float* __restrict__ qsc,
    const float* __restrict__ qbi, const float* __restrict__ qmu,
    const float* __restrict__ qva,
    const float* __restrict__ kdw, const float* __restrict__ ksc,
    const float* __restrict__ kbi, const float* __restrict__ kmu,
    const float* __restrict__ kva,
    const float* __restrict__ vdw, const float* __restrict__ vsc,
    const float* __restrict__ vbi, const float* __restrict__ vmu,
    const float* __restrict__ vva,
    const float* __restrict__ Wq, const float* __restrict__ Wk,
    const float* __restrict__ Wv)
{
    const int b = blockIdx.y;
    const int bxb = blockIdx.x;
    const int tid = threadIdx.y * 48 + threadIdx.x;

    if (bxb >= 294) {                      // ---- W fp32 -> fp16 conversion ----
        if (b != 0) return;
        int wb = bxb - 294;                // 0..143; 48 blocks per W
        const float* Ws = (wb < 48) ? Wq : (wb < 96) ? Wk : Wv;
        __half* Wd = (wb < 48) ? g_wq : (wb < 96) ? g_wk : g_wv;
        float s = (wb < 48) ? QSCALE : 1.0f;
        int local = (wb % 48) * 768 + tid * 4;
        float4 v = *(const float4*)&Ws[local];
        __half2* o = (__half2*)&Wd[local];
        o[0] = __floats2half2_rn(v.x * s, v.y * s);
        o[1] = __floats2half2_rn(v.z * s, v.w * s);
        return;
    }

    const int p = bxb * 4 + threadIdx.y;
    const int c = threadIdx.x * 4;
    const float* xb = x + (size_t)b * L_ * C_ + c;

    if (p < 784) {
        float4 wq[9];
        #pragma unroll
        for (int t = 0; t < 9; t++) wq[t] = *(const float4*)&qdw[t * C_ + c];

        int y0 = (p / 56) * 4, xx = p % 56;
        float4 acc[4];
        #pragma unroll
        for (int i = 0; i < 4; i++) acc[i] = make_float4(0.f, 0.f, 0.f, 0.f);
        #pragma unroll
        for (int r = 0; r < 6; r++) {
            int iy = y0 - 1 + r;
            if ((unsigned)iy >= (unsigned)S_) continue;
            #pragma unroll
            for (int dx = 0; dx < 3; dx++) {
                int ix = xx + dx - 1;
                if ((unsigned)ix >= (unsigned)S_) continue;
                float4 xv = *(const float4*)&xb[(size_t)(iy * S_ + ix) * C_];
                #pragma unroll
                for (int i = 0; i < 4; i++) {
                    int dy = r - i;
                    if (dy < 0 || dy > 2) continue;
                    float4 wv = wq[dy * 3 + dx];
                    acc[i].x += xv.x * wv.x; acc[i].y += xv.y * wv.y;
                    acc[i].z += xv.z * wv.z; acc[i].w += xv.w * wv.w;
                }
            }
        }
        float4 scv = *(const float4*)&qsc[c];
        float4 vav = *(const float4*)&qva[c];
        float4 muv = *(const float4*)&qmu[c];
        float4 biv = *(const float4*)&qbi[c];
        float a0 = scv.x * rsqrtf(vav.x + 1e-5f);
        float a1 = scv.y * rsqrtf(vav.y + 1e-5f);
        float a2 = scv.z * rsqrtf(vav.z + 1e-5f);
        float a3 = scv.w * rsqrtf(vav.w + 1e-5f);
        #pragma unroll
        for (int i = 0; i < 4; i++) {
            __half2* o = (__half2*)&g_hq[((size_t)b * L_ + (y0 + i) * S_ + xx) * C_ + c];
            o[0] = __floats2half2_rn((acc[i].x - muv.x) * a0 + biv.x,
                                     (acc[i].y - muv.y) * a1 + biv.y);
            o[1] = __floats2half2_rn((acc[i].z - muv.z) * a2 + biv.z,
                                     (acc[i].w - muv.w) * a3 + biv.w);
        }
    } else {
        int p2 = p - 784;
        int y0 = (p2 / SO_) * 2, xx = p2 % SO_;

        // pass 1: k
        {
            float4 w9[9];
            #pragma unroll
            for (int t = 0; t < 9; t++) w9[t] = *(const float4*)&kdw[t * C_ + c];
            float4 ka[2];
            ka[0] = make_float4(0.f, 0.f, 0.f, 0.f);
            ka[1] = make_float4(0.f, 0.f, 0.f, 0.f);
            #pragma unroll
            for (int r = 0; r < 5; r++) {
                int iy = 2 * y0 + r;
                if (iy >= S_) continue;
                #pragma unroll
                for (int dx = 0; dx < 3; dx++) {
                    int ix = 2 * xx + dx;
                    if (ix >= S_) continue;
                    float4 xv = *(const float4*)&xb[(size_t)(iy * S_ + ix) * C_];
                    #pragma unroll
                    for (int i = 0; i < 2; i++) {
                        int dy = r - 2 * i;
                        if (dy < 0 || dy > 2) continue;
                        float4 w = w9[dy * 3 + dx];
                        ka[i].x += xv.x * w.x; ka[i].y += xv.y * w.y;
                        ka[i].z += xv.z * w.z; ka[i].w += xv.w * w.w;
                    }
                }
            }
            float4 scv = *(const float4*)&ksc[c];
            float4 vav = *(const float4*)&kva[c];
            float4 muv = *(const float4*)&kmu[c];
            float4 biv = *(const float4*)&kbi[c];
            float a0 = scv.x * rsqrtf(vav.x + 1e-5f);
            float a1 = scv.y * rsqrtf(vav.y + 1e-5f);
            float a2 = scv.z * rsqrtf(vav.z + 1e-5f);
            float a3 = scv.w * rsqrtf(vav.w + 1e-5f);
            #pragma unroll
            for (int i = 0; i < 2; i++) {
                __half2* o = (__half2*)&g_hk[((size_t)b * L2_ + (y0 + i) * SO_ + xx) * C_ + c];
                o[0] = __floats2half2_rn((ka[i].x - muv.x) * a0 + biv.x,
                                         (ka[i].y - muv.y) * a1 + biv.y);
                o[1] = __floats2half2_rn((ka[i].z - muv.z) * a2 + biv.z,
                                         (ka[i].w - muv.w) * a3 + biv.w);
            }
        }
        // pass 2: v (same x taps — L1 hits)
        {
            float4 w9[9];
            #pragma unroll
            for (int t = 0; t < 9; t++) w9[t] = *(const float4*)&vdw[t * C_ + c];
            float4 va[2];
            va[0] = make_float4(0.f, 0.f, 0.f, 0.f);
            va[1] = make_float4(0.f, 0.f, 0.f, 0.f);
            #pragma unroll
            for (int r = 0; r < 5; r++) {
                int iy = 2 * y0 + r;
                if (iy >= S_) continue;
                #pragma unroll
                for (int dx = 0; dx < 3; dx++) {
                    int ix = 2 * xx + dx;
                    if (ix >= S_) continue;
                    float4 xv = *(const float4*)&xb[(size_t)(iy * S_ + ix) * C_];
                    #pragma unroll
                    for (int i = 0; i < 2; i++) {
                        int dy = r - 2 * i;
                        if (dy < 0 || dy > 2) continue;
                        float4 w = w9[dy * 3 + dx];
                        va[i].x += xv.x * w.x; va[i].y += xv.y * w.y;
                        va[i].z += xv.z * w.z; va[i].w += xv.w * w.w;
                    }
                }
            }
            float4 scv = *(const float4*)&vsc[c];
            float4 vav = *(const float4*)&vva[c];
            float4 muv = *(const float4*)&vmu[c];
            float4 biv = *(const float4*)&vbi[c];
            float a0 = scv.x * rsqrtf(vav.x + 1e-5f);
            float a1 = scv.y * rsqrtf(vav.y + 1e-5f);
            float a2 = scv.z * rsqrtf(vav.z + 1e-5f);
            float a3 = scv.w * rsqrtf(vav.w + 1e-5f);
            #pragma unroll
            for (int i = 0; i < 2; i++) {
                __half2* o = (__half2*)&g_hv[((size_t)b * L2_ + (y0 + i) * SO_ + xx) * C_ + c];
                o[0] = __floats2half2_rn((va[i].x - muv.x) * a0 + biv.x,
                                         (va[i].y - muv.y) * a1 + biv.y);
                o[1] = __floats2half2_rn((va[i].z - muv.z) * a2 + biv.z,
                                         (va[i].w - muv.w) * a3 + biv.w);
            }
        }
    }
}

// ---------------- pointwise 1x1 conv (k and v ONLY; q fused into attn) ----------------
#define PW_SMEM (128*200*2 + 192*72*2)
__global__ void __launch_bounds__(256) pw_all()
{
    const __half* A; const __half* Wh; __half* Cp; int m0;
    int bx = blockIdx.x;
    if (bx < 49) { A = g_hk; Cp = g_k; Wh = g_wk; m0 = bx * 128; }
    else         { A = g_hv; Cp = g_v; Wh = g_wv; m0 = (bx - 49) * 128; }
    const int n0 = blockIdx.y * 64;

    extern __shared__ char smc[];
    __half* As = (__half*)smc;
    __half* Bs = (__half*)(smc + 128 * 200 * 2);

    const int tid = threadIdx.x;
    const int w = tid >> 5, lane = tid & 31;
    const int g = lane >> 2, tg = lane & 3;
    const int lm = lane >> 3, lr = lane & 7;
    const uint32_t sAs = smem_u32(As), sBs = smem_u32(Bs);

    #pragma unroll
    for (int i = 0; i < 12; i++) {
        int idx = tid + i * 256;
        int r = idx / 24, ch = idx % 24;
        cp16(&As[r * 200 + ch * 8], A + (size_t)(m0 + r) * C_ + ch * 8);
    }
    #pragma unroll
    for (int i = 0; i < 6; i++) {
        int idx = tid + i * 256;
        int k = idx >> 3, nq = idx & 7;
        cp16(&Bs[k * 72 + nq * 8], Wh + (size_t)k * C_ + n0 + nq * 8);
    }
    CP_COMMIT();
    CP_WAIT0();
    __syncthreads();

    float Cv[8][4];
    #pragma unroll
    for (int i = 0; i < 8; i++)
        #pragma unroll
        for (int j = 0; j < 4; j++) Cv[i][j] = 0.f;

    const uint32_t aBase = sAs + (uint32_t)(((w * 16 + (lm & 1) * 8 + lr) * 200
                                             + (lm >> 1) * 8) * 2);
    const uint32_t bRow  = (uint32_t)(((lm & 1) * 8 + lr) * 72) * 2;
    #pragma unroll
    for (int ks = 0; ks < 12; ks++) {
        uint32_t a0, a1, a2, a3;
        LDM_X4(a0, a1, a2, a3, aBase + ks * 32);
        #pragma unroll
        for (int nfp = 0; nfp < 4; nfp++) {
            uint32_t b00, b01, b10, b11;
            uint32_t ba = sBs + (uint32_t)(ks * 16 * 72 * 2) + bRow
                        + (uint32_t)(((nfp * 2 + (lm >> 1)) * 8) * 2);
            LDM_X4T(b00, b01, b10, b11, ba);
            mma16(Cv[nfp * 2],     a0, a1, a2, a3, b00, b01);
            mma16(Cv[nfp * 2 + 1], a0, a1, a2, a3, b10, b11);
        }
    }

    const int r0 = 16 * w + g;
    __half* o0 = Cp + (size_t)(m0 + r0) * C_ + n0;
    __half* o1 = o0 + (size_t)8 * C_;
    #pragma unroll
    for (int nf = 0; nf < 8; nf++) {
        *(__half2*)&o0[nf * 8 + 2 * tg] = __floats2half2_rn(Cv[nf][0], Cv[nf][1]);
        *(__half2*)&o1[nf * 8 + 2 * tg] = __floats2half2_rn(Cv[nf][2], Cv[nf][3]);
    }
}

// ---------------- flash attention with double-buffered fused q-projection ----------------
// Smem (384 rows x 72 halfs) holds TWO staging sets during the prologue:
//   S0: hq -> rows [0,128), Wq -> rows [128,192)
//   S1: hq -> rows [192,320), Wq -> rows [320,384)
// Main loop unchanged (Ks = rows [128,256), Vs = rows [256,384)).
#define NKT 13
#define ATTN_SMEM ((128*72 + 4*64*72) * 2)
__global__ void __launch_bounds__(256, 2) attn_mma(float* __restrict__ out)
{
    extern __shared__ char smc[];
    __half* Qs = (__half*)smc;
    __half* Ks = Qs + 128 * 72;
    __half* Vs = Ks + 2 * 64 * 72;

    const int tid = threadIdx.x;
    const int w = tid >> 5, lane = tid & 31;
    const int g = lane >> 2, tg = lane & 3;
    const int lm = lane >> 3, lr = lane & 7;
    const int q0 = blockIdx.x * 128;
    const int h = blockIdx.y, b = blockIdx.z;

    const __half* hqp = g_hq + (size_t)b * L_ * C_;
    const __half* kp = g_k + (size_t)b * L2_ * C_ + h * D_;
    const __half* vp = g_v + (size_t)b * L2_ * C_ + h * D_;

    const uint32_t aFragOff = (uint32_t)((((lm & 1) * 8 + lr) * 72 + (lm >> 1) * 8) * 2)
                            + (uint32_t)((w * 16) * 72 * 2);
    const uint32_t bRowW = (uint32_t)(((lm & 1) * 8 + lr) * 72) * 2;   // k-row (trans B)
    const uint32_t bRowK = (uint32_t)(((lm >> 1) * 8 + lr) * 72 * 2);  // QK: j rows
    const uint32_t bRowV = (uint32_t)(((lm & 1) * 8 + lr) * 72 * 2);   // PV: k rows, trans
    const uint32_t sBase = smem_u32(Qs);

    // staging helpers (row offsets in units of 72-half rows)
    auto stage_hq = [&](int rowoff, int cch) {
        __half* dst = Qs + rowoff * 72;
        #pragma unroll
        for (int p = 0; p < 4; p++) {
            int id = tid + p * 256;
            int r = id >> 3, off = (id & 7) * 8;
            int rg = q0 + r; if (rg > L_ - 1) rg = L_ - 1;
            cp16(&dst[r * 72 + off], hqp + (size_t)rg * C_ + cch * 64 + off);
        }
    };
    auto stage_wq = [&](int rowoff, int cch) {
        __half* dst = Qs + rowoff * 72;
        #pragma unroll
        for (int p = 0; p < 2; p++) {
            int id = tid + p * 256;
            int kk = id >> 3, off = (id & 7) * 8;
            cp16(&dst[kk * 72 + off], g_wq + (size_t)(cch * 64 + kk) * C_ + h * D_ + off);
        }
    };

    float Qacc[8][4];
    #pragma unroll
    for (int i = 0; i < 8; i++)
        #pragma unroll
        for (int j = 0; j < 4; j++) Qacc[i][j] = 0.f;

    auto qproj_compute = [&](int hqRow, int wqRow) {
        const uint32_t aB = sBase + (uint32_t)(hqRow * 72 * 2) + aFragOff;
        const uint32_t bB = sBase + (uint32_t)(wqRow * 72 * 2);
        #pragma unroll
        for (int ks = 0; ks < 4; ks++) {
            uint32_t a0, a1, a2, a3;
            LDM_X4(a0, a1, a2, a3, aB + ks * 32);
            #pragma unroll
            for (int nfp = 0; nfp < 4; nfp++) {
                uint32_t b00, b01, b10, b11;
                uint32_t ba = bB + (uint32_t)(ks * 16 * 72 * 2) + bRowW
                            + (uint32_t)(((nfp * 2 + (lm >> 1)) * 8) * 2);
                LDM_X4T(b00, b01, b10, b11, ba);
                mma16(Qacc[nfp * 2],     a0, a1, a2, a3, b00, b01);
                mma16(Qacc[nfp * 2 + 1], a0, a1, a2, a3, b10, b11);
            }
        }
    };

    // issue chunk0 -> S0, chunk1 -> S1
    stage_hq(0, 0);   stage_wq(128, 0); CP_COMMIT();
    stage_hq(192, 1); stage_wq(320, 1); CP_COMMIT();
    CP_WAIT1();              // chunk0 ready
    __syncthreads();
    qproj_compute(0, 128);   // chunk0
    __syncthreads();         // S0 free
    stage_hq(0, 2); stage_wq(128, 2); CP_COMMIT();   // chunk2 -> S0
    CP_WAIT1();              // chunk1 ready
    __syncthreads();
    qproj_compute(192, 320); // chunk1 (no conflict with in-flight chunk2 writes)
    CP_WAIT0();              // chunk2 ready
    __syncthreads();
    qproj_compute(0, 128);   // chunk2
    __syncthreads();         // all reads done before KV overwrites Ks0/Vs0

    // pack fp32 C-fragments -> fp16 A-fragments for QK^T (Wq pre-scaled by QSCALE)
    uint32_t Qa[4][4];
    #pragma unroll
    for (int ks = 0; ks < 4; ks++) {
        Qa[ks][0] = packh2(Qacc[2 * ks][0],     Qacc[2 * ks][1]);
        Qa[ks][1] = packh2(Qacc[2 * ks][2],     Qacc[2 * ks][3]);
        Qa[ks][2] = packh2(Qacc[2 * ks + 1][0], Qacc[2 * ks + 1][1]);
        Qa[ks][3] = packh2(Qacc[2 * ks + 1][2], Qacc[2 * ks + 1][3]);
    }

    // issue K+V tile 0 (buf 0)
    #pragma unroll
    for (int p = 0; p < 2; p++) {
        int id = tid + p * 256;
        int j = id >> 3, off = (id & 7) * 8;
        cp16(&Ks[j * 72 + off], kp + (size_t)j * C_ + off);
        cp16(&Vs[j * 72 + off], vp + (size_t)j * C_ + off);
    }
    CP_COMMIT();

    float Ov[8][4];
    #pragma unroll
    for (int i = 0; i < 8; i++)
        #pragma unroll
        for (int j = 0; j < 4; j++) Ov[i][j] = 0.f;
    float s0 = 0.f, s1 = 0.f;

    for (int kt = 0; kt < NKT; kt++) {
        CP_WAIT0();
        __syncthreads();

        if (kt + 1 < NKT) {
            int nb = (kt + 1) & 1;
            int j0n = (kt + 1) * 64;
            __half* Kb = Ks + nb * (64 * 72);
            __half* Vb = Vs + nb * (64 * 72);
            #pragma unroll
            for (int p = 0; p < 2; p++) {
                int id = tid + p * 256;
                int j = id >> 3, off = (id & 7) * 8;
                int jg = j0n + j; if (jg > L2_ - 1) jg = L2_ - 1;
                cp16(&Kb[j * 72 + off], kp + (size_t)jg * C_ + off);
                cp16(&Vb[j * 72 + off], vp + (size_t)jg * C_ + off);
            }
            CP_COMMIT();
        }

        const uint32_t sK = smem_u32(Ks + (kt & 1) * (64 * 72));
        const uint32_t sV = smem_u32(Vs + (kt & 1) * (64 * 72));

        // S = Q K^T : warp 16 x 64
        float Sc[8][4];
        #pragma unroll
        for (int i = 0; i < 8; i++)
            #pragma unroll
            for (int j = 0; j < 4; j++) Sc[i][j] = 0.f;
        #pragma unroll
        for (int ks = 0; ks < 4; ks++) {
            #pragma unroll
            for (int nfp = 0; nfp < 4; nfp++) {
                uint32_t b00, b01, b10, b11;
                uint32_t ba = sK + (uint32_t)(nfp * 16 * 72 * 2) + bRowK
                            + (uint32_t)((ks * 16 + (lm & 1) * 8) * 2);
                LDM_X4(b00, b01, b10, b11, ba);
                mma16(Sc[nfp * 2],     Qa[ks][0], Qa[ks][1], Qa[ks][2], Qa[ks][3], b00, b01);
                mma16(Sc[nfp * 2 + 1], Qa[ks][0], Qa[ks][1], Qa[ks][2], Qa[ks][3], b10, b11);
            }
        }

        int j0 = kt * 64;
        if (j0 + 64 > L2_) {             // mask invalid keys: exp2(-1e4) == 0
            #pragma unroll
            for (int nf = 0; nf < 8; nf++) {
                int c0 = j0 + nf * 8 + 2 * tg;
                if (c0 >= L2_)     { Sc[nf][0] = -1e4f; Sc[nf][2] = -1e4f; }
                if (c0 + 1 >= L2_) { Sc[nf][1] = -1e4f; Sc[nf][3] = -1e4f; }
            }
        }

        // P = exp2(S) directly (scores bounded); accumulate row sums in fp32
        uint32_t Pa[8][2];
        #pragma unroll
        for (int nf = 0; nf < 8; nf++) {
            float p00 = ex2(Sc[nf][0]);
            float p01 = ex2(Sc[nf][1]);
            float p10 = ex2(Sc[nf][2]);
            float p11 = ex2(Sc[nf][3]);
            s0 += p00 + p01; s1 += p10 + p11;
            Pa[nf][0] = packh2(p00, p01);
            Pa[nf][1] = packh2(p10, p11);
        }

        // O += P V   (A = P regs, B = V via ldmatrix.trans)
        #pragma unroll
        for (int ks = 0; ks < 4; ks++) {
            uint32_t a0 = Pa[2 * ks][0],     a1 = Pa[2 * ks][1];
            uint32_t a2 = Pa[2 * ks + 1][0], a3 = Pa[2 * ks + 1][1];
            #pragma unroll
            for (int dfp = 0; dfp < 4; dfp++) {
                uint32_t b00, b01, b10, b11;
                uint32_t ba = sV + (uint32_t)(ks * 16 * 72 * 2) + bRowV
                            + (uint32_t)(((dfp * 2 + (lm >> 1)) * 8) * 2);
                LDM_X4T(b00, b01, b10, b11, ba);
                mma16(Ov[dfp * 2],     a0, a1, a2, a3, b00, b01);
                mma16(Ov[dfp * 2 + 1], a0, a1, a2, a3, b10, b11);
            }
        }
    }

    // single final reduction of row sums over the quad
    s0 += __shfl_xor_sync(0xffffffffu, s0, 1);
    s0 += __shfl_xor_sync(0xffffffffu, s0, 2);
    s1 += __shfl_xor_sync(0xffffffffu, s1, 1);
    s1 += __shfl_xor_sync(0xffffffffu, s1, 2);

    // epilogue (fp32 output) — guard rows past L_ (last q-tile is ragged)
    float i0 = 1.f / s0, i1 = 1.f / s1;
    int rg0 = q0 + 16 * w + g;
    if (rg0 < L_) {
        float* o = out + ((size_t)b * L_ + rg0) * C_ + h * D_;
        #pragma unroll
        for (int df = 0; df < 8; df++)
            *(float2*)&o[df * 8 + 2 * tg] =
                make_float2(Ov[df][0] * i0, Ov[df][1] * i0);
    }
    int rg1 = rg0 + 8;
    if (rg1 < L_) {
        float* o = out + ((size_t)b * L_ + rg1) * C_ + h * D_;
        #pragma unroll
        for (int df = 0; df < 8; df++)
            *(float2*)&o[df * 8 + 2 * tg] =
                make_float2(Ov[df][2] * i1, Ov[df][3] * i1);
    }
}

// ---------------- launch ----------------
extern "C" void kernel_launch(void* const* d_in, const int* in_sizes, int n_in,
                              void* d_out, int out_size)
{
    const float* x       = (const float*)d_in[0];
    const float* q_dw    = (const float*)d_in[1];
    const float* q_scale = (const float*)d_in[2];
    const float* q_bias  = (const float*)d_in[3];
    const float* q_mean  = (const float*)d_in[4];
    const float* q_var   = (const float*)d_in[5];
    const float* q_pw    = (const float*)d_in[6];
    const float* k_dw    = (const float*)d_in[7];
    const float* k_scale = (const float*)d_in[8];
    const float* k_bias  = (const float*)d_in[9];
    const float* k_mean  = (const float*)d_in[10];
    const float* k_var   = (const float*)d_in[11];
    const float* k_pw    = (const float*)d_in[12];
    const float* v_dw    = (const float*)d_in[13];
    const float* v_scale = (const float*)d_in[14];
    const float* v_bias  = (const float*)d_in[15];
    const float* v_mean  = (const float*)d_in[16];
    const float* v_var   = (const float*)d_in[17];
    const float* v_pw    = (const float*)d_in[18];
    float* out = (float*)d_out;

    cudaFuncSetAttribute(pw_all,
                         cudaFuncAttributeMaxDynamicSharedMemorySize, PW_SMEM);
    cudaFuncSetAttribute(attn_mma,
                         cudaFuncAttributeMaxDynamicSharedMemorySize, ATTN_SMEM);

    dw_all<<<dim3(438, B_), dim3(48, 4)>>>(x,
        q_dw, q_scale, q_bias, q_mean, q_var,
        k_dw, k_scale, k_bias, k_mean, k_var,
        v_dw, v_scale, v_bias, v_mean, v_var,
        q_pw, k_pw, v_pw);

    pw_all<<<dim3(98, 3), 256, PW_SMEM>>>();

    attn_mma<<<dim3((L_ + 127) / 128, H_, B_), 256, ATTN_SMEM>>>(out);
}